// round 7
// baseline (speedup 1.0000x reference)
#include <cuda_runtime.h>

// SSIM loss: pred/target fp32 (8,8,3,256,256) -> scalar 1 - mean(ssim_map)
// 192 planes of 256x256. Depthwise 11x11 Gaussian (sigma=1.5), separable.
//
// Sum/diff basis: s = x+y, d = x-y. Four convolutions (s, d, s^2, d^2):
//   A = conv(s) = mu_x + mu_y,  B = conv(d) = mu_x - mu_y
//   S1 = conv(s^2) = Sxx + 2Sxy + Syy,  S2 = conv(d^2) = Sxx - 2Sxy + Syy
//   4 mu_xy = A^2 - B^2;  2(mu_x^2+mu_y^2) = A^2 + B^2
//   4 Sxy   = S1 - S2;    2(Sxx+Syy)       = S1 + S2

#define HW       256
#define PLANE    (HW * HW)
#define NPLANES  192
#define TILES_X  8
#define TILES_Y  8
#define NBLOCKS  (TILES_X * TILES_Y * NPLANES)   // 12288
#define NTHREADS 256
#define NPIX     12582912.0                       // 192*256*256

#define ROWW     48                               // staged raw row width (floats)
#define NROWS    42                               // 32 out + 2*5 halo

__device__ float        g_partials[NBLOCKS];
__device__ unsigned int g_ticket = 0;            // reset by last block (replay-safe)

// Normalized Gaussian weights for ws=11, sigma=1.5.
#define GW0 0.00102838f
#define GW1 0.00759872f
#define GW2 0.03600084f
#define GW3 0.10936034f
#define GW4 0.21300566f
#define GW5 0.26601220f

__global__ __launch_bounds__(NTHREADS, 5) void ssim_main(
    const float* __restrict__ pred, const float* __restrict__ targ,
    float* __restrict__ out)
{
    // Horizontal-conv intermediates: 4 quantities x 42 rows x 32 cols (21504 B)
    __shared__ float s_int[4][NROWS * 32];
    // Raw staged s/d tiles and vertical results have disjoint lifetimes.
    __shared__ union {
        float raw[2][NROWS * ROWW];   // 16128 B  (s, d), zero-padded halo
        float fin[4][32 * 32];        // 16384 B  (A, B, S1, S2)
    } u;
    __shared__ float s_red[8];
    __shared__ int   s_last;

    const int tid = threadIdx.x;
    const int ox = blockIdx.x * 32;
    const int oy = blockIdx.y * 32;
    const int plane = blockIdx.z;
    const float* __restrict__ px = pred + (size_t)plane * PLANE;
    const float* __restrict__ py = targ + (size_t)plane * PLANE;

    const float W[11] = {GW0, GW1, GW2, GW3, GW4, GW5, GW4, GW3, GW2, GW1, GW0};

    // ---- Phase 0: coalesced float4 staging of s = x+y, d = x-y ----
    // 42 rows x 12 float4 = 504 tasks. smem col j <-> gmem col ox-8+j.
    for (int task = tid; task < NROWS * 12; task += NTHREADS) {
        const int r  = task / 12;
        const int v  = task - r * 12;
        const int gy = oy + r - 5;
        const int gx = ox - 8 + 4 * v;

        float4 xv = make_float4(0.f, 0.f, 0.f, 0.f);
        float4 yv = xv;
        if ((unsigned)gy < (unsigned)HW && (unsigned)gx < (unsigned)HW) {
            xv = __ldg(reinterpret_cast<const float4*>(px + gy * HW + gx));
            yv = __ldg(reinterpret_cast<const float4*>(py + gy * HW + gx));
        }
        const int o = r * ROWW + 4 * v;
        *reinterpret_cast<float4*>(&u.raw[0][o]) =
            make_float4(xv.x + yv.x, xv.y + yv.y, xv.z + yv.z, xv.w + yv.w);
        *reinterpret_cast<float4*>(&u.raw[1][o]) =
            make_float4(xv.x - yv.x, xv.y - yv.y, xv.z - yv.z, xv.w - yv.w);
    }
    __syncthreads();

    // ---- Phase A: horizontal conv of s, d, s^2, d^2 ----
    // 42 rows x 8 col-groups (4 outputs) = 336 tasks.
    for (int task = tid; task < NROWS * 8; task += NTHREADS) {
        const int r  = task >> 3;
        const int c0 = (task & 7) * 4;
        const int base = r * ROWW + c0;
        float t[20], v[14];

        // s
        #pragma unroll
        for (int vi = 0; vi < 5; vi++)
            *reinterpret_cast<float4*>(&t[4 * vi]) =
                *reinterpret_cast<const float4*>(&u.raw[0][base + 4 * vi]);
        {
            float a0 = 0.f, a1 = 0.f, a2 = 0.f, a3 = 0.f;
            #pragma unroll
            for (int k = 0; k < 11; k++) {
                a0 = fmaf(W[k], t[3 + k],     a0);
                a1 = fmaf(W[k], t[3 + k + 1], a1);
                a2 = fmaf(W[k], t[3 + k + 2], a2);
                a3 = fmaf(W[k], t[3 + k + 3], a3);
            }
            *reinterpret_cast<float4*>(&s_int[0][r * 32 + c0]) = make_float4(a0, a1, a2, a3);
        }
        // s^2
        #pragma unroll
        for (int i = 0; i < 14; i++) v[i] = t[3 + i] * t[3 + i];
        {
            float a0 = 0.f, a1 = 0.f, a2 = 0.f, a3 = 0.f;
            #pragma unroll
            for (int k = 0; k < 11; k++) {
                a0 = fmaf(W[k], v[k],     a0);
                a1 = fmaf(W[k], v[k + 1], a1);
                a2 = fmaf(W[k], v[k + 2], a2);
                a3 = fmaf(W[k], v[k + 3], a3);
            }
            *reinterpret_cast<float4*>(&s_int[2][r * 32 + c0]) = make_float4(a0, a1, a2, a3);
        }
        // d
        #pragma unroll
        for (int vi = 0; vi < 5; vi++)
            *reinterpret_cast<float4*>(&t[4 * vi]) =
                *reinterpret_cast<const float4*>(&u.raw[1][base + 4 * vi]);
        {
            float a0 = 0.f, a1 = 0.f, a2 = 0.f, a3 = 0.f;
            #pragma unroll
            for (int k = 0; k < 11; k++) {
                a0 = fmaf(W[k], t[3 + k],     a0);
                a1 = fmaf(W[k], t[3 + k + 1], a1);
                a2 = fmaf(W[k], t[3 + k + 2], a2);
                a3 = fmaf(W[k], t[3 + k + 3], a3);
            }
            *reinterpret_cast<float4*>(&s_int[1][r * 32 + c0]) = make_float4(a0, a1, a2, a3);
        }
        // d^2
        #pragma unroll
        for (int i = 0; i < 14; i++) v[i] = t[3 + i] * t[3 + i];
        {
            float a0 = 0.f, a1 = 0.f, a2 = 0.f, a3 = 0.f;
            #pragma unroll
            for (int k = 0; k < 11; k++) {
                a0 = fmaf(W[k], v[k],     a0);
                a1 = fmaf(W[k], v[k + 1], a1);
                a2 = fmaf(W[k], v[k + 2], a2);
                a3 = fmaf(W[k], v[k + 3], a3);
            }
            *reinterpret_cast<float4*>(&s_int[3][r * 32 + c0]) = make_float4(a0, a1, a2, a3);
        }
    }
    __syncthreads();   // u.raw dead, u.fin live below

    // ---- Phase B: vertical conv, 8-output register blocking ----
    // 4 quantities x 4 row-groups x 32 cols = 512 tasks (2 per thread).
    for (int task = tid; task < 512; task += NTHREADS) {
        const int q   = task >> 7;
        const int rem = task & 127;
        const int rg  = rem >> 5;
        const int c   = rem & 31;
        const int r0  = rg * 8;

        float v[18];
        #pragma unroll
        for (int k = 0; k < 18; k++) v[k] = s_int[q][(r0 + k) * 32 + c];

        #pragma unroll
        for (int j = 0; j < 8; j++) {
            float a = 0.f;
            #pragma unroll
            for (int k = 0; k < 11; k++) a = fmaf(W[k], v[j + k], a);
            u.fin[q][(r0 + j) * 32 + c] = a;
        }
    }
    __syncthreads();

    // ---- Phase C: SSIM map + block reduction ----
    float lsum = 0.0f;
    #pragma unroll
    for (int i = 0; i < 4; i++) {
        const int idx = tid + i * NTHREADS;
        const float A  = u.fin[0][idx];
        const float B  = u.fin[1][idx];
        const float S1 = u.fin[2][idx];
        const float S2 = u.fin[3][idx];

        const float A2 = A * A;
        const float B2 = B * B;
        const float mxy  = 0.25f * (A2 - B2);          // mu_x * mu_y
        const float msum = 0.50f * (A2 + B2);          // mu_x^2 + mu_y^2
        const float sxy  = 0.25f * (S1 - S2) - mxy;    // sigma_xy
        const float ssum = fmaxf(0.50f * (S1 + S2) - msum, 0.0f);

        const float num = (2.0f * mxy + 1e-4f) * (2.0f * sxy + 9e-4f);
        const float den = (msum + 1e-4f) * (ssum + 9e-4f);
        float s = num / (den + 1e-8f);
        if (!isfinite(s)) s = 0.0f;
        lsum += s;
    }

    #pragma unroll
    for (int o = 16; o > 0; o >>= 1)
        lsum += __shfl_down_sync(0xffffffffu, lsum, o);
    if ((tid & 31) == 0) s_red[tid >> 5] = lsum;
    __syncthreads();

    if (tid == 0) {
        float v = 0.0f;
        #pragma unroll
        for (int w = 0; w < 8; w++) v += s_red[w];
        const int bid = (blockIdx.z * TILES_Y + blockIdx.y) * TILES_X + blockIdx.x;
        g_partials[bid] = v;
        // Release atomic: drains this block's prior stores to L2 WITHOUT the
        // L1D flush a gpu-scope __threadfence would emit (CCTL.IVALL -- the
        // R2/R3 regression).
        unsigned t;
        asm volatile("atom.release.gpu.add.u32 %0, [%1], 1;"
                     : "=r"(t) : "l"(&g_ticket) : "memory");
        s_last = (t == NBLOCKS - 1);
    }
    __syncthreads();

    // ---- Last block: deterministic final reduction (fixed order). Every
    // writer's release reached L2 before its ticket increment; __ldcg reads
    // L2 directly, so the values are guaranteed current.
    if (s_last) {
        __shared__ double sr[NTHREADS];
        const float4* p4 = reinterpret_cast<const float4*>(g_partials);
        double a0 = 0.0, a1 = 0.0, a2 = 0.0, a3 = 0.0;
        #pragma unroll 4
        for (int i = tid; i < NBLOCKS / 4; i += NTHREADS) {
            const float4 v = __ldcg(p4 + i);
            a0 += (double)v.x; a1 += (double)v.y; a2 += (double)v.z; a3 += (double)v.w;
        }
        sr[tid] = (a0 + a1) + (a2 + a3);
        __syncthreads();
        #pragma unroll
        for (int off = NTHREADS / 2; off > 0; off >>= 1) {
            if (tid < off) sr[tid] += sr[tid + off];
            __syncthreads();
        }
        if (tid == 0) {
            out[0] = 1.0f - (float)(sr[0] / NPIX);
            g_ticket = 0;   // reset for next graph replay
        }
    }
}

extern "C" void kernel_launch(void* const* d_in, const int* in_sizes, int n_in,
                              void* d_out, int out_size)
{
    const float* pred = (const float*)d_in[0];
    const float* targ = (const float*)d_in[1];
    dim3 grid(TILES_X, TILES_Y, NPLANES);
    ssim_main<<<grid, NTHREADS>>>(pred, targ, (float*)d_out);
}

// round 8
// speedup vs baseline: 1.1840x; 1.1840x over previous
#include <cuda_runtime.h>

// SSIM loss: pred/target fp32 (8,8,3,256,256) -> scalar 1 - mean(ssim_map)
// 192 planes of 256x256. Depthwise 11x11 Gaussian (sigma=1.5), separable.
//
// Sum/diff basis: s = x+y, d = x-y. Four convolutions (s, d, s^2, d^2):
//   A = conv(s) = mu_x + mu_y,  B = conv(d) = mu_x - mu_y
//   S1 = conv(s^2) = Sxx + 2Sxy + Syy,  S2 = conv(d^2) = Sxx - 2Sxy + Syy
//   4 mu_xy = A^2 - B^2;  2(mu_x^2+mu_y^2) = A^2 + B^2
//   4 Sxy   = S1 - S2;    2(Sxx+Syy)       = S1 + S2
//
// Global reduction: fixed-point u64 RED.ADD (associative -> deterministic in
// any arrival order; fire-and-forget -> NO per-block fence/release, which
// measured +20us at this grid). Finalize kernel reads/resets the accumulator.

#define HW       256
#define PLANE    (HW * HW)
#define NPLANES  192
#define TILES_X  8
#define TILES_Y  8
#define NTHREADS 256
#define NPIX     12582912.0                       // 192*256*256
#define FXSCALE  4294967296.0                     // 2^32

#define ROWW     48                               // staged raw row width (floats)
#define NROWS    42                               // 32 out + 2*5 halo

__device__ unsigned long long g_isum = 0ULL;      // reset by finalize (replay-safe)

// Normalized Gaussian weights for ws=11, sigma=1.5.
#define GW0 0.00102838f
#define GW1 0.00759872f
#define GW2 0.03600084f
#define GW3 0.10936034f
#define GW4 0.21300566f
#define GW5 0.26601220f

__global__ __launch_bounds__(NTHREADS, 5) void ssim_main(
    const float* __restrict__ pred, const float* __restrict__ targ)
{
    // Horizontal-conv intermediates: 4 quantities x 42 rows x 32 cols (21504 B)
    __shared__ float s_int[4][NROWS * 32];
    // Raw staged s/d tiles and vertical results have disjoint lifetimes.
    __shared__ union {
        float raw[2][NROWS * ROWW];   // 16128 B  (s, d), zero-padded halo
        float fin[4][32 * 32];        // 16384 B  (A, B, S1, S2)
    } u;
    __shared__ float s_red[8];

    const int tid = threadIdx.x;
    const int ox = blockIdx.x * 32;
    const int oy = blockIdx.y * 32;
    const int plane = blockIdx.z;
    const float* __restrict__ px = pred + (size_t)plane * PLANE;
    const float* __restrict__ py = targ + (size_t)plane * PLANE;

    const float W[11] = {GW0, GW1, GW2, GW3, GW4, GW5, GW4, GW3, GW2, GW1, GW0};

    // ---- Phase 0: coalesced float4 staging of s = x+y, d = x-y ----
    // 42 rows x 12 float4 = 504 tasks. smem col j <-> gmem col ox-8+j.
    for (int task = tid; task < NROWS * 12; task += NTHREADS) {
        const int r  = task / 12;
        const int v  = task - r * 12;
        const int gy = oy + r - 5;
        const int gx = ox - 8 + 4 * v;

        float4 xv = make_float4(0.f, 0.f, 0.f, 0.f);
        float4 yv = xv;
        if ((unsigned)gy < (unsigned)HW && (unsigned)gx < (unsigned)HW) {
            xv = __ldg(reinterpret_cast<const float4*>(px + gy * HW + gx));
            yv = __ldg(reinterpret_cast<const float4*>(py + gy * HW + gx));
        }
        const int o = r * ROWW + 4 * v;
        *reinterpret_cast<float4*>(&u.raw[0][o]) =
            make_float4(xv.x + yv.x, xv.y + yv.y, xv.z + yv.z, xv.w + yv.w);
        *reinterpret_cast<float4*>(&u.raw[1][o]) =
            make_float4(xv.x - yv.x, xv.y - yv.y, xv.z - yv.z, xv.w - yv.w);
    }
    __syncthreads();

    // ---- Phase A: horizontal conv of s, d, s^2, d^2 ----
    // 42 rows x 8 col-groups (4 outputs) = 336 tasks.
    for (int task = tid; task < NROWS * 8; task += NTHREADS) {
        const int r  = task >> 3;
        const int c0 = (task & 7) * 4;
        const int base = r * ROWW + c0;
        float t[20], v[14];

        // s
        #pragma unroll
        for (int vi = 0; vi < 5; vi++)
            *reinterpret_cast<float4*>(&t[4 * vi]) =
                *reinterpret_cast<const float4*>(&u.raw[0][base + 4 * vi]);
        {
            float a0 = 0.f, a1 = 0.f, a2 = 0.f, a3 = 0.f;
            #pragma unroll
            for (int k = 0; k < 11; k++) {
                a0 = fmaf(W[k], t[3 + k],     a0);
                a1 = fmaf(W[k], t[3 + k + 1], a1);
                a2 = fmaf(W[k], t[3 + k + 2], a2);
                a3 = fmaf(W[k], t[3 + k + 3], a3);
            }
            *reinterpret_cast<float4*>(&s_int[0][r * 32 + c0]) = make_float4(a0, a1, a2, a3);
        }
        // s^2
        #pragma unroll
        for (int i = 0; i < 14; i++) v[i] = t[3 + i] * t[3 + i];
        {
            float a0 = 0.f, a1 = 0.f, a2 = 0.f, a3 = 0.f;
            #pragma unroll
            for (int k = 0; k < 11; k++) {
                a0 = fmaf(W[k], v[k],     a0);
                a1 = fmaf(W[k], v[k + 1], a1);
                a2 = fmaf(W[k], v[k + 2], a2);
                a3 = fmaf(W[k], v[k + 3], a3);
            }
            *reinterpret_cast<float4*>(&s_int[2][r * 32 + c0]) = make_float4(a0, a1, a2, a3);
        }
        // d
        #pragma unroll
        for (int vi = 0; vi < 5; vi++)
            *reinterpret_cast<float4*>(&t[4 * vi]) =
                *reinterpret_cast<const float4*>(&u.raw[1][base + 4 * vi]);
        {
            float a0 = 0.f, a1 = 0.f, a2 = 0.f, a3 = 0.f;
            #pragma unroll
            for (int k = 0; k < 11; k++) {
                a0 = fmaf(W[k], t[3 + k],     a0);
                a1 = fmaf(W[k], t[3 + k + 1], a1);
                a2 = fmaf(W[k], t[3 + k + 2], a2);
                a3 = fmaf(W[k], t[3 + k + 3], a3);
            }
            *reinterpret_cast<float4*>(&s_int[1][r * 32 + c0]) = make_float4(a0, a1, a2, a3);
        }
        // d^2
        #pragma unroll
        for (int i = 0; i < 14; i++) v[i] = t[3 + i] * t[3 + i];
        {
            float a0 = 0.f, a1 = 0.f, a2 = 0.f, a3 = 0.f;
            #pragma unroll
            for (int k = 0; k < 11; k++) {
                a0 = fmaf(W[k], v[k],     a0);
                a1 = fmaf(W[k], v[k + 1], a1);
                a2 = fmaf(W[k], v[k + 2], a2);
                a3 = fmaf(W[k], v[k + 3], a3);
            }
            *reinterpret_cast<float4*>(&s_int[3][r * 32 + c0]) = make_float4(a0, a1, a2, a3);
        }
    }
    __syncthreads();   // u.raw dead, u.fin live below

    // ---- Phase B: vertical conv, 8-output register blocking ----
    // 4 quantities x 4 row-groups x 32 cols = 512 tasks (2 per thread).
    for (int task = tid; task < 512; task += NTHREADS) {
        const int q   = task >> 7;
        const int rem = task & 127;
        const int rg  = rem >> 5;
        const int c   = rem & 31;
        const int r0  = rg * 8;

        float v[18];
        #pragma unroll
        for (int k = 0; k < 18; k++) v[k] = s_int[q][(r0 + k) * 32 + c];

        #pragma unroll
        for (int j = 0; j < 8; j++) {
            float a = 0.f;
            #pragma unroll
            for (int k = 0; k < 11; k++) a = fmaf(W[k], v[j + k], a);
            u.fin[q][(r0 + j) * 32 + c] = a;
        }
    }
    __syncthreads();

    // ---- Phase C: SSIM map + block reduction ----
    float lsum = 0.0f;
    #pragma unroll
    for (int i = 0; i < 4; i++) {
        const int idx = tid + i * NTHREADS;
        const float A  = u.fin[0][idx];
        const float B  = u.fin[1][idx];
        const float S1 = u.fin[2][idx];
        const float S2 = u.fin[3][idx];

        const float A2 = A * A;
        const float B2 = B * B;
        const float mxy  = 0.25f * (A2 - B2);          // mu_x * mu_y
        const float msum = 0.50f * (A2 + B2);          // mu_x^2 + mu_y^2
        const float sxy  = 0.25f * (S1 - S2) - mxy;    // sigma_xy
        const float ssum = fmaxf(0.50f * (S1 + S2) - msum, 0.0f);

        const float num = (2.0f * mxy + 1e-4f) * (2.0f * sxy + 9e-4f);
        const float den = (msum + 1e-4f) * (ssum + 9e-4f);
        float s = num / (den + 1e-8f);
        if (!isfinite(s)) s = 0.0f;
        lsum += s;
    }

    #pragma unroll
    for (int o = 16; o > 0; o >>= 1)
        lsum += __shfl_down_sync(0xffffffffu, lsum, o);
    if ((tid & 31) == 0) s_red[tid >> 5] = lsum;
    __syncthreads();
    if (tid == 0) {
        float v = 0.0f;
        #pragma unroll
        for (int w = 0; w < 8; w++) v += s_red[w];
        // Fixed-point RED.ADD.u64: fire-and-forget, associative, deterministic.
        atomicAdd(&g_isum, (unsigned long long)__double2ll_rn((double)v * FXSCALE));
    }
}

// Trivial finalize: one load, one store, reset accumulator for graph replay.
__global__ void ssim_finalize(float* __restrict__ out)
{
    const double s = (double)g_isum * (1.0 / FXSCALE);
    out[0] = 1.0f - (float)(s / NPIX);
    g_isum = 0ULL;
}

extern "C" void kernel_launch(void* const* d_in, const int* in_sizes, int n_in,
                              void* d_out, int out_size)
{
    const float* pred = (const float*)d_in[0];
    const float* targ = (const float*)d_in[1];
    dim3 grid(TILES_X, TILES_Y, NPLANES);
    ssim_main<<<grid, NTHREADS>>>(pred, targ);
    ssim_finalize<<<1, 1>>>((float*)d_out);
}

// round 9
// speedup vs baseline: 1.2401x; 1.0474x over previous
#include <cuda_runtime.h>

// SSIM loss: pred/target fp32 (8,8,3,256,256) -> scalar 1 - mean(ssim_map)
// 192 planes of 256x256. Depthwise 11x11 Gaussian (sigma=1.5), separable.
//
// Sum/diff basis: s = x+y, d = x-y. Four convolutions (s, d, s^2, d^2):
//   A = conv(s), B = conv(d), S1 = conv(s^2), S2 = conv(d^2)
//   4 mu_xy = A^2 - B^2;  2(mu_x^2+mu_y^2) = A^2 + B^2
//   4 Sxy   = S1 - S2;    2(Sxx+Syy)       = S1 + S2
//
// Global reduction: fixed-point u64 RED.ADD (associative -> deterministic,
// fire-and-forget -> no per-block fence; a fence/release costs +20us here).

#define HW       256
#define PLANE    (HW * HW)
#define NPLANES  192
#define TILES_X  8
#define TILES_Y  8
#define NTHREADS 256
#define NPIX     12582912.0                       // 192*256*256
#define FXSCALE  4294967296.0                     // 2^32

#define ROWW     48                               // staged raw row width (floats)
#define NROWS    42                               // 32 out + 2*5 halo

__device__ unsigned long long g_isum = 0ULL;      // reset by finalize (replay-safe)

// Normalized Gaussian weights for ws=11, sigma=1.5.
#define GW0 0.00102838f
#define GW1 0.00759872f
#define GW2 0.03600084f
#define GW3 0.10936034f
#define GW4 0.21300566f
#define GW5 0.26601220f

__global__ __launch_bounds__(NTHREADS, 6) void ssim_main(
    const float* __restrict__ pred, const float* __restrict__ targ)
{
    // Horizontal-conv intermediates: 4 quantities x 42 rows x 32 cols (21504 B)
    __shared__ float s_int[4][NROWS * 32];
    // Raw staged s/d tiles (dead after Phase A, but no reuse needed anymore)
    __shared__ float s_raw[2][NROWS * ROWW];      // 16128 B
    __shared__ float s_red[8];

    const int tid = threadIdx.x;
    const int ox = blockIdx.x * 32;
    const int oy = blockIdx.y * 32;
    const int plane = blockIdx.z;
    const float* __restrict__ px = pred + (size_t)plane * PLANE;
    const float* __restrict__ py = targ + (size_t)plane * PLANE;

    const float W[11] = {GW0, GW1, GW2, GW3, GW4, GW5, GW4, GW3, GW2, GW1, GW0};

    // ---- Phase 0: coalesced float4 staging of s = x+y, d = x-y ----
    // 42 rows x 12 float4 = 504 tasks. smem col j <-> gmem col ox-8+j.
    for (int task = tid; task < NROWS * 12; task += NTHREADS) {
        const int r  = task / 12;
        const int v  = task - r * 12;
        const int gy = oy + r - 5;
        const int gx = ox - 8 + 4 * v;

        float4 xv = make_float4(0.f, 0.f, 0.f, 0.f);
        float4 yv = xv;
        if ((unsigned)gy < (unsigned)HW && (unsigned)gx < (unsigned)HW) {
            xv = __ldg(reinterpret_cast<const float4*>(px + gy * HW + gx));
            yv = __ldg(reinterpret_cast<const float4*>(py + gy * HW + gx));
        }
        const int o = r * ROWW + 4 * v;
        *reinterpret_cast<float4*>(&s_raw[0][o]) =
            make_float4(xv.x + yv.x, xv.y + yv.y, xv.z + yv.z, xv.w + yv.w);
        *reinterpret_cast<float4*>(&s_raw[1][o]) =
            make_float4(xv.x - yv.x, xv.y - yv.y, xv.z - yv.z, xv.w - yv.w);
    }
    __syncthreads();

    // ---- Phase A: horizontal conv of s, d, s^2, d^2 ----
    // 42 rows x 8 col-groups (4 outputs) = 336 tasks.
    for (int task = tid; task < NROWS * 8; task += NTHREADS) {
        const int r  = task >> 3;
        const int c0 = (task & 7) * 4;
        const int base = r * ROWW + c0;
        float t[20], v[14];

        // s
        #pragma unroll
        for (int vi = 0; vi < 5; vi++)
            *reinterpret_cast<float4*>(&t[4 * vi]) =
                *reinterpret_cast<const float4*>(&s_raw[0][base + 4 * vi]);
        {
            float a0 = 0.f, a1 = 0.f, a2 = 0.f, a3 = 0.f;
            #pragma unroll
            for (int k = 0; k < 11; k++) {
                a0 = fmaf(W[k], t[3 + k],     a0);
                a1 = fmaf(W[k], t[3 + k + 1], a1);
                a2 = fmaf(W[k], t[3 + k + 2], a2);
                a3 = fmaf(W[k], t[3 + k + 3], a3);
            }
            *reinterpret_cast<float4*>(&s_int[0][r * 32 + c0]) = make_float4(a0, a1, a2, a3);
        }
        // s^2
        #pragma unroll
        for (int i = 0; i < 14; i++) v[i] = t[3 + i] * t[3 + i];
        {
            float a0 = 0.f, a1 = 0.f, a2 = 0.f, a3 = 0.f;
            #pragma unroll
            for (int k = 0; k < 11; k++) {
                a0 = fmaf(W[k], v[k],     a0);
                a1 = fmaf(W[k], v[k + 1], a1);
                a2 = fmaf(W[k], v[k + 2], a2);
                a3 = fmaf(W[k], v[k + 3], a3);
            }
            *reinterpret_cast<float4*>(&s_int[2][r * 32 + c0]) = make_float4(a0, a1, a2, a3);
        }
        // d
        #pragma unroll
        for (int vi = 0; vi < 5; vi++)
            *reinterpret_cast<float4*>(&t[4 * vi]) =
                *reinterpret_cast<const float4*>(&s_raw[1][base + 4 * vi]);
        {
            float a0 = 0.f, a1 = 0.f, a2 = 0.f, a3 = 0.f;
            #pragma unroll
            for (int k = 0; k < 11; k++) {
                a0 = fmaf(W[k], t[3 + k],     a0);
                a1 = fmaf(W[k], t[3 + k + 1], a1);
                a2 = fmaf(W[k], t[3 + k + 2], a2);
                a3 = fmaf(W[k], t[3 + k + 3], a3);
            }
            *reinterpret_cast<float4*>(&s_int[1][r * 32 + c0]) = make_float4(a0, a1, a2, a3);
        }
        // d^2
        #pragma unroll
        for (int i = 0; i < 14; i++) v[i] = t[3 + i] * t[3 + i];
        {
            float a0 = 0.f, a1 = 0.f, a2 = 0.f, a3 = 0.f;
            #pragma unroll
            for (int k = 0; k < 11; k++) {
                a0 = fmaf(W[k], v[k],     a0);
                a1 = fmaf(W[k], v[k + 1], a1);
                a2 = fmaf(W[k], v[k + 2], a2);
                a3 = fmaf(W[k], v[k + 3], a3);
            }
            *reinterpret_cast<float4*>(&s_int[3][r * 32 + c0]) = make_float4(a0, a1, a2, a3);
        }
    }
    __syncthreads();

    // ---- Phase B+C merged: vertical conv (4 rows x 4 quantities in regs)
    // then SSIM directly -- no fin round-trip, no extra barrier.
    // 256 tasks: tid -> (rowgroup of 4, col).
    float lsum = 0.0f;
    {
        const int rg = tid >> 5;          // 0..7
        const int c  = tid & 31;
        const int r0 = rg * 4;

        float res[4][4];
        #pragma unroll
        for (int q = 0; q < 4; q++) {
            float v[14];
            #pragma unroll
            for (int k = 0; k < 14; k++) v[k] = s_int[q][(r0 + k) * 32 + c];
            #pragma unroll
            for (int j = 0; j < 4; j++) {
                float a = 0.f;
                #pragma unroll
                for (int k = 0; k < 11; k++) a = fmaf(W[k], v[j + k], a);
                res[q][j] = a;
            }
        }

        #pragma unroll
        for (int j = 0; j < 4; j++) {
            const float A  = res[0][j];
            const float B  = res[1][j];
            const float S1 = res[2][j];
            const float S2 = res[3][j];

            const float A2 = A * A;
            const float B2 = B * B;
            const float mxy  = 0.25f * (A2 - B2);          // mu_x * mu_y
            const float msum = 0.50f * (A2 + B2);          // mu_x^2 + mu_y^2
            const float sxy  = 0.25f * (S1 - S2) - mxy;    // sigma_xy
            const float ssum = fmaxf(0.50f * (S1 + S2) - msum, 0.0f);

            const float num = (2.0f * mxy + 1e-4f) * (2.0f * sxy + 9e-4f);
            const float den = (msum + 1e-4f) * (ssum + 9e-4f);
            float s = num / (den + 1e-8f);
            if (!isfinite(s)) s = 0.0f;
            lsum += s;
        }
    }

    #pragma unroll
    for (int o = 16; o > 0; o >>= 1)
        lsum += __shfl_down_sync(0xffffffffu, lsum, o);
    if ((tid & 31) == 0) s_red[tid >> 5] = lsum;
    __syncthreads();
    if (tid == 0) {
        float v = 0.0f;
        #pragma unroll
        for (int w = 0; w < 8; w++) v += s_red[w];
        // Fixed-point RED.ADD.u64: fire-and-forget, associative, deterministic.
        atomicAdd(&g_isum, (unsigned long long)__double2ll_rn((double)v * FXSCALE));
    }
}

// Trivial finalize: one load, one store, reset accumulator for graph replay.
__global__ void ssim_finalize(float* __restrict__ out)
{
    const double s = (double)g_isum * (1.0 / FXSCALE);
    out[0] = 1.0f - (float)(s / NPIX);
    g_isum = 0ULL;
}

extern "C" void kernel_launch(void* const* d_in, const int* in_sizes, int n_in,
                              void* d_out, int out_size)
{
    const float* pred = (const float*)d_in[0];
    const float* targ = (const float*)d_in[1];
    dim3 grid(TILES_X, TILES_Y, NPLANES);
    ssim_main<<<grid, NTHREADS>>>(pred, targ);
    ssim_finalize<<<1, 1>>>((float*)d_out);
}